// round 8
// baseline (speedup 1.0000x reference)
#include <cuda_runtime.h>
#include <cstdint>

#define DEV __device__ __forceinline__

namespace {

constexpr int LEADS = 12;
constexpr int FIN   = 512;
constexpr int HID   = 256;
constexpr int OUTF  = 128;
constexpr int TOTAL_B = 16384;
constexpr int TOTAL_ROWS = TOTAL_B * LEADS;   // 196608

constexpr int SAMP = 10;       // samples per CTA
constexpr int RT   = 128;      // padded row-tile (10*12=120 -> 128)
constexpr int KC   = 16;       // K chunk streamed through SMEM
constexpr int XSS  = 20;       // Xs row stride (floats): 20 % 8 == 4 -> conflict-free A frags
constexpr int WSS  = 264;      // Ws row stride: 264 % 32 == 8 -> conflict-free B frags
constexpr int HS   = 260;      // Hbuf row stride: 260 % 32 == 4 -> conflict-free A frags
constexpr int NT   = 256;      // threads (8 warps, 64x64 warp tiles)

constexpr int OFF_H = 0;
constexpr int SZ_H  = RT * HS;            // 33280 floats
constexpr int OFF_X = OFF_H + SZ_H;
constexpr int SZ_X  = 2 * RT * XSS;       // 5120
constexpr int OFF_W = OFF_X + SZ_X;
constexpr int SZ_W  = 2 * KC * WSS;       // 8448
constexpr int OFF_A = OFF_W + SZ_W;
constexpr int SMEM_FLOATS = OFF_A + 160;  // A matrix + pad
constexpr int SMEM_BYTES  = SMEM_FLOATS * 4;   // ~188 KB

DEV uint32_t f2tf(float f) {
  uint32_t u;
  asm("cvt.rna.tf32.f32 %0, %1;" : "=r"(u) : "f"(f));
  return u;
}
DEV float tfv(float f) { return __uint_as_float(f2tf(f)); }

DEV void mma8(float d[4], const uint32_t a[4], const uint32_t b[2]) {
  asm volatile(
    "mma.sync.aligned.m16n8k8.row.col.f32.tf32.tf32.f32 "
    "{%0,%1,%2,%3},{%4,%5,%6,%7},{%8,%9},{%0,%1,%2,%3};"
    : "+f"(d[0]), "+f"(d[1]), "+f"(d[2]), "+f"(d[3])
    : "r"(a[0]), "r"(a[1]), "r"(a[2]), "r"(a[3]), "r"(b[0]), "r"(b[1]));
}

// Warp-level 64x(NTiles*8) GEMM over one K chunk of KC.
// As: warp's 64-row block base (row-major, stride astr, tf32 values)
// Bs: warp's col block base within Ws ([k][n], stride WSS, tf32 values)
template<int NTILES>
DEV void gemm_chunk(const float* __restrict__ As, int astr,
                    const float* __restrict__ Bs,
                    int lane, float acc[4][8][4]) {
  const int r = lane >> 2, c = lane & 3;
  #pragma unroll
  for (int k0 = 0; k0 < KC; k0 += 8) {
    uint32_t a[4][4];
    #pragma unroll
    for (int mi = 0; mi < 4; mi++) {
      const float* ap = As + (mi * 16 + r) * astr + k0 + c;
      a[mi][0] = __float_as_uint(ap[0]);
      a[mi][1] = __float_as_uint(ap[8 * astr]);
      a[mi][2] = __float_as_uint(ap[4]);
      a[mi][3] = __float_as_uint(ap[8 * astr + 4]);
    }
    #pragma unroll
    for (int nj = 0; nj < NTILES; nj++) {
      const float* bp = Bs + (k0 + c) * WSS + nj * 8 + r;
      uint32_t b[2];
      b[0] = __float_as_uint(bp[0]);
      b[1] = __float_as_uint(bp[4 * WSS]);
      #pragma unroll
      for (int mi = 0; mi < 4; mi++) mma8(acc[mi][nj], a[mi], b);
    }
  }
}

__global__ void __launch_bounds__(NT, 1)
ecg_fused_kernel(const float* __restrict__ x,
                 const float* __restrict__ W1, const float* __restrict__ b1,
                 const float* __restrict__ W2, const float* __restrict__ b2,
                 const float* __restrict__ W3, const float* __restrict__ b3,
                 float* __restrict__ out)
{
  extern __shared__ float sm[];
  float* Hb  = sm + OFF_H;
  float* Xs  = sm + OFF_X;
  float* Wsm = sm + OFF_W;
  float* Am  = sm + OFF_A;

  const int tid  = threadIdx.x;
  const int lane = tid & 31;
  const int wid  = tid >> 5;
  const int wm   = wid >> 2;   // 0..1 row block (64 rows each)
  const int wn   = wid & 3;    // 0..3 col block
  const int s0    = blockIdx.x * SAMP;
  const int nsamp = min(SAMP, TOTAL_B - s0);
  const int row0  = s0 * LEADS;

  // ---- Build normalized adjacency (matches reference _norm_adj) ----
  if (tid == 0) {
    const int ci[15] = {0,0,1,0,1,2,0,1,1,2,6,7,8,9,10};
    const int cj[15] = {1,2,2,3,3,3,4,4,5,5,7,8,9,10,11};
    float ae[12][12];
    for (int i = 0; i < 12; i++)
      for (int j = 0; j < 12; j++) ae[i][j] = 0.f;
    for (int p = 0; p < 15; p++) { ae[ci[p]][cj[p]] = 1.f; ae[cj[p]][ci[p]] = 1.f; }
    for (int i = 0; i < 12; i++) ae[i][i] = 2.f;
    float dinv[12];
    for (int i = 0; i < 12; i++) {
      float s = 0.f;
      for (int j = 0; j < 12; j++) s += ae[i][j];
      dinv[i] = (float)(1.0 / sqrt((double)s));
    }
    for (int i = 0; i < 12; i++)
      for (int j = 0; j < 12; j++)
        Am[i * 12 + j] = dinv[i] * ae[i][j] * dinv[j];
  }

  float acc[4][8][4];

  // Epilogue: store accumulators into Hbuf
  auto store_acc = [&](int wcols, int ntiles) {
    const int r = lane >> 2, c2 = (lane & 3) * 2;
    #pragma unroll
    for (int mi = 0; mi < 4; mi++)
      #pragma unroll
      for (int nj = 0; nj < 8; nj++) {
        if (nj >= ntiles) break;
        int row = wm * 64 + mi * 16 + r;
        int col = wn * wcols + nj * 8 + c2;
        *reinterpret_cast<float2*>(Hb + row * HS + col) =
            make_float2(acc[mi][nj][0], acc[mi][nj][1]);
        *reinterpret_cast<float2*>(Hb + (row + 8) * HS + col) =
            make_float2(acc[mi][nj][2], acc[mi][nj][3]);
      }
  };

  // Lead-mix + bias + relu + tf32 requantize, in place in Hbuf
  auto mix_relu = [&](int ncolshift, const float* bias) {
    const int ncol  = 1 << ncolshift;
    const int ntask = nsamp * ncol;
    for (int t = tid; t < ntask; t += NT) {
      int s = t >> ncolshift, cc = t & (ncol - 1);
      float* base = Hb + (s * LEADS) * HS + cc;
      float v[12];
      #pragma unroll
      for (int l = 0; l < 12; l++) v[l] = base[l * HS];
      float bv = bias[cc];
      #pragma unroll
      for (int n = 0; n < 12; n++) {
        float h = bv;
        #pragma unroll
        for (int m = 0; m < 12; m++) h = fmaf(Am[n * 12 + m], v[m], h);
        h = fmaxf(h, 0.f);
        base[n * HS] = tfv(h);
      }
    }
  };

  // ======================= Layer 1: X(128x512) @ W1(512x256) =======================
  {
    #pragma unroll
    for (int mi = 0; mi < 4; mi++)
      for (int nj = 0; nj < 8; nj++)
        for (int q = 0; q < 4; q++) acc[mi][nj][q] = 0.f;

    float4 px[2], pw[4];

    // X stage: 128 rows x 16 cols = 512 float4; 2 per thread
    auto ldx = [&](int kb) {
      #pragma unroll
      for (int i = 0; i < 2; i++) {
        int idx = tid + i * NT;
        int xr = idx >> 2, xc4 = idx & 3;
        int gr = row0 + xr;
        if (gr < TOTAL_ROWS)
          px[i] = *reinterpret_cast<const float4*>(x + (size_t)gr * FIN + kb + xc4 * 4);
        else
          px[i] = make_float4(0.f, 0.f, 0.f, 0.f);
      }
    };
    auto stx = [&](int buf) {
      #pragma unroll
      for (int i = 0; i < 2; i++) {
        int idx = tid + i * NT;
        int xr = idx >> 2, xc4 = idx & 3;
        float4 v = px[i], o;
        o.x = tfv(v.x); o.y = tfv(v.y); o.z = tfv(v.z); o.w = tfv(v.w);
        *reinterpret_cast<float4*>(Xs + buf * (RT * XSS) + xr * XSS + xc4 * 4) = o;
      }
    };
    // W stage: 16 rows x 256 cols = 1024 float4; 4 per thread
    auto ldw = [&](int kb) {
      #pragma unroll
      for (int i = 0; i < 4; i++) {
        int idx = tid + i * NT;
        int k = idx >> 6, c4 = idx & 63;
        pw[i] = *reinterpret_cast<const float4*>(W1 + (size_t)(kb + k) * HID + c4 * 4);
      }
    };
    auto stw = [&](int buf) {
      #pragma unroll
      for (int i = 0; i < 4; i++) {
        int idx = tid + i * NT;
        int k = idx >> 6, c4 = idx & 63;
        float4 v = pw[i], o;
        o.x = tfv(v.x); o.y = tfv(v.y); o.z = tfv(v.z); o.w = tfv(v.w);
        *reinterpret_cast<float4*>(Wsm + buf * (KC * WSS) + k * WSS + c4 * 4) = o;
      }
    };

    ldx(0); ldw(0);
    stx(0); stw(0);
    __syncthreads();
    constexpr int NC = FIN / KC;   // 32 chunks
    for (int ck = 0; ck < NC; ck++) {
      if (ck + 1 < NC) { ldx((ck + 1) * KC); ldw((ck + 1) * KC); }
      const float* As = Xs + (ck & 1) * (RT * XSS) + (wm * 64) * XSS;
      const float* Bs = Wsm + (ck & 1) * (KC * WSS) + wn * 64;
      gemm_chunk<8>(As, XSS, Bs, lane, acc);
      if (ck + 1 < NC) { stx((ck + 1) & 1); stw((ck + 1) & 1); }
      __syncthreads();
    }
    store_acc(64, 8);
    __syncthreads();
    mix_relu(8, b1);
    __syncthreads();
  }

  // ======================= Layer 2: H(128x256) @ W2(256x256) =======================
  {
    #pragma unroll
    for (int mi = 0; mi < 4; mi++)
      for (int nj = 0; nj < 8; nj++)
        for (int q = 0; q < 4; q++) acc[mi][nj][q] = 0.f;

    float4 pw[4];
    auto ldw2 = [&](int kb) {
      #pragma unroll
      for (int i = 0; i < 4; i++) {
        int idx = tid + i * NT;
        int k = idx >> 6, c4 = idx & 63;
        pw[i] = *reinterpret_cast<const float4*>(W2 + (size_t)(kb + k) * HID + c4 * 4);
      }
    };
    auto stw2 = [&](int buf) {
      #pragma unroll
      for (int i = 0; i < 4; i++) {
        int idx = tid + i * NT;
        int k = idx >> 6, c4 = idx & 63;
        float4 v = pw[i], o;
        o.x = tfv(v.x); o.y = tfv(v.y); o.z = tfv(v.z); o.w = tfv(v.w);
        *reinterpret_cast<float4*>(Wsm + buf * (KC * WSS) + k * WSS + c4 * 4) = o;
      }
    };

    ldw2(0); stw2(0);
    __syncthreads();
    constexpr int NC2 = HID / KC;   // 16 chunks
    for (int ck = 0; ck < NC2; ck++) {
      if (ck + 1 < NC2) ldw2((ck + 1) * KC);
      const float* As = Hb + (wm * 64) * HS + ck * KC;
      const float* Bs = Wsm + (ck & 1) * (KC * WSS) + wn * 64;
      gemm_chunk<8>(As, HS, Bs, lane, acc);
      if (ck + 1 < NC2) stw2((ck + 1) & 1);
      __syncthreads();
    }
    store_acc(64, 8);
    __syncthreads();
    mix_relu(8, b2);
    __syncthreads();
  }

  // ======================= Layer 3: H(128x256) @ W3(256x128) + pool =======================
  {
    #pragma unroll
    for (int mi = 0; mi < 4; mi++)
      for (int nj = 0; nj < 8; nj++)
        for (int q = 0; q < 4; q++) acc[mi][nj][q] = 0.f;

    float4 pw3[2];
    auto ldw3 = [&](int kb) {
      #pragma unroll
      for (int i = 0; i < 2; i++) {
        int idx = tid + i * NT;
        int k = idx >> 5, c4 = idx & 31;   // 16 rows x 32 float4s
        pw3[i] = *reinterpret_cast<const float4*>(W3 + (size_t)(kb + k) * OUTF + c4 * 4);
      }
    };
    auto stw3 = [&](int buf) {
      #pragma unroll
      for (int i = 0; i < 2; i++) {
        int idx = tid + i * NT;
        int k = idx >> 5, c4 = idx & 31;
        float4 v = pw3[i], o;
        o.x = tfv(v.x); o.y = tfv(v.y); o.z = tfv(v.z); o.w = tfv(v.w);
        *reinterpret_cast<float4*>(Wsm + buf * (KC * WSS) + k * WSS + c4 * 4) = o;
      }
    };

    ldw3(0); stw3(0);
    __syncthreads();
    constexpr int NC3 = HID / KC;   // 16 chunks
    for (int ck = 0; ck < NC3; ck++) {
      if (ck + 1 < NC3) ldw3((ck + 1) * KC);
      const float* As = Hb + (wm * 64) * HS + ck * KC;
      const float* Bs = Wsm + (ck & 1) * (KC * WSS) + wn * 32;
      gemm_chunk<4>(As, HS, Bs, lane, acc);
      if (ck + 1 < NC3) stw3((ck + 1) & 1);
      __syncthreads();
    }
    store_acc(32, 4);
    __syncthreads();

    // Final: lead-mix + b3, then mean/max pool over leads, write (B, 2*OUTF)
    const int ntask = nsamp * OUTF;
    for (int t = tid; t < ntask; t += NT) {
      int s = t >> 7, cc = t & (OUTF - 1);
      const float* base = Hb + (s * LEADS) * HS + cc;
      float v[12];
      #pragma unroll
      for (int l = 0; l < 12; l++) v[l] = base[l * HS];
      float bv = b3[cc];
      float mean = 0.f;
      float mx = __int_as_float(0xff800000);   // -inf
      #pragma unroll
      for (int n = 0; n < 12; n++) {
        float h = bv;
        #pragma unroll
        for (int m = 0; m < 12; m++) h = fmaf(Am[n * 12 + m], v[m], h);
        mean += h;
        mx = fmaxf(mx, h);
      }
      size_t ob = (size_t)(s0 + s) * (2 * OUTF);
      out[ob + cc] = mean * (1.f / 12.f);
      out[ob + OUTF + cc] = mx;
    }
  }
}

} // anonymous namespace

extern "C" void kernel_launch(void* const* d_in, const int* in_sizes, int n_in,
                              void* d_out, int out_size) {
  const float* x  = (const float*)d_in[0];
  const float* W1 = (const float*)d_in[1];
  const float* b1 = (const float*)d_in[2];
  const float* W2 = (const float*)d_in[3];
  const float* b2 = (const float*)d_in[4];
  const float* W3 = (const float*)d_in[5];
  const float* b3 = (const float*)d_in[6];
  float* out = (float*)d_out;

  cudaFuncSetAttribute(ecg_fused_kernel,
                       cudaFuncAttributeMaxDynamicSharedMemorySize, SMEM_BYTES);

  const int grid = (TOTAL_B + SAMP - 1) / SAMP;   // 1639
  ecg_fused_kernel<<<grid, NT, SMEM_BYTES>>>(x, W1, b1, W2, b2, W3, b3, out);
}

// round 11
// speedup vs baseline: 2.1503x; 2.1503x over previous
#include <cuda_runtime.h>
#include <cuda_fp16.h>
#include <cstdint>

#define DEV __device__ __forceinline__

namespace {

constexpr int LEADS = 12;
constexpr int FIN   = 512;
constexpr int HID   = 256;
constexpr int OUTF  = 128;
constexpr int TOTAL_B = 16384;
constexpr int TOTAL_ROWS = TOTAL_B * LEADS;   // 196608

constexpr int SAMP = 10;       // samples per CTA -> 120 rows, pad to 128
constexpr int NT   = 256;      // 8 warps, 64x64 warp tiles
constexpr int KC   = 32;       // K halves per streamed chunk (2 x k16 mma steps)

// strides in halves. Conflict-free requirement for frag loads:
// word-stride pattern r*(S/2) + c distinct mod 32 -> (S/2) mod 8 == 4.
constexpr int SA  = 40;        // staged A (X) row stride: 40/2=20, 20%8=4 ok
constexpr int SB  = 40;        // staged B (W^T) row stride
constexpr int SHH = 264;       // H buffer row stride: 264/2=132, 132%8=4 ok

constexpr int XBUF = 128 * SA;     // 5120 halves per buffer
constexpr int WBUF = 256 * SB;     // 10240 halves per buffer

// SMEM layout (halves)
constexpr int OFF_HH = 0;                       // 128 x 264 = 33792
constexpr int OFF_XS = 128 * SHH;               // 33792: 2 x XBUF
constexpr int OFF_WS = OFF_XS + 2 * XBUF;       // 44032: 2 x WBUF
constexpr int SMEM_HALVES = OFF_WS + 2 * WBUF;  // 64512
constexpr int SMEM_BYTES  = SMEM_HALVES * 2;    // 129024 B

// ---- compile-time normalized adjacency (matches reference _norm_adj) ----
constexpr double csqrt(double x) {
  double g = x > 1.0 ? x : 1.0;
  for (int i = 0; i < 64; i++) g = 0.5 * (g + x / g);
  return g;
}
struct AMt { float a[12][12]; };
constexpr AMt make_am() {
  AMt m{};
  const int ci[15] = {0,0,1,0,1,2,0,1,1,2,6,7,8,9,10};
  const int cj[15] = {1,2,2,3,3,3,4,4,5,5,7,8,9,10,11};
  double ae[12][12] = {};
  for (int p = 0; p < 15; p++) { ae[ci[p]][cj[p]] = 1.0; ae[cj[p]][ci[p]] = 1.0; }
  for (int i = 0; i < 12; i++) ae[i][i] = 2.0;
  double deg[12] = {};
  for (int i = 0; i < 12; i++)
    for (int j = 0; j < 12; j++) deg[i] += ae[i][j];
  for (int i = 0; i < 12; i++)
    for (int j = 0; j < 12; j++)
      m.a[i][j] = (float)(ae[i][j] / (csqrt(deg[i]) * csqrt(deg[j])));
  return m;
}
// __device__ constexpr: usable (and folded) in device code without
// --expt-relaxed-constexpr, which this harness does not pass.
__device__ constexpr AMt AMC = make_am();

DEV uint32_t ld32h(const __half* p) {
  return *reinterpret_cast<const uint32_t*>(p);
}
DEV uint32_t h2u(__half2 h) { return *reinterpret_cast<uint32_t*>(&h); }

DEV void mma16(float d[4], const uint32_t a[4], uint32_t b0, uint32_t b1) {
  asm volatile(
    "mma.sync.aligned.m16n8k16.row.col.f32.f16.f16.f32 "
    "{%0,%1,%2,%3},{%4,%5,%6,%7},{%8,%9},{%0,%1,%2,%3};"
    : "+f"(d[0]), "+f"(d[1]), "+f"(d[2]), "+f"(d[3])
    : "r"(a[0]), "r"(a[1]), "r"(a[2]), "r"(a[3]), "r"(b0), "r"(b1));
}

// Warp-level 64 x (NTILES*8) GEMM over one KC=32 chunk (two k16 steps).
// As: warp's 64-row block base, [row][k] halves stride sa.
// Bs: warp's n-block base, [n][k] halves stride sb.
template<int NTILES>
DEV void gemm_chunk(const __half* __restrict__ As, int sa,
                    const __half* __restrict__ Bs, int sb,
                    int lane, float acc[4][8][4]) {
  const int g = lane >> 2, t2 = (lane & 3) * 2;
  #pragma unroll
  for (int k0 = 0; k0 < KC; k0 += 16) {
    uint32_t a[4][4];
    #pragma unroll
    for (int mi = 0; mi < 4; mi++) {
      const __half* ap = As + (mi * 16 + g) * sa + k0 + t2;
      a[mi][0] = ld32h(ap);
      a[mi][1] = ld32h(ap + 8 * sa);
      a[mi][2] = ld32h(ap + 8);
      a[mi][3] = ld32h(ap + 8 * sa + 8);
    }
    #pragma unroll
    for (int nj = 0; nj < NTILES; nj++) {
      const __half* bp = Bs + (nj * 8 + g) * sb + k0 + t2;
      uint32_t b0 = ld32h(bp);
      uint32_t b1 = ld32h(bp + 8);
      #pragma unroll
      for (int mi = 0; mi < 4; mi++) mma16(acc[mi][nj], a[mi], b0, b1);
    }
  }
}

__global__ void __launch_bounds__(NT, 1)
ecg_fused_kernel(const float* __restrict__ x,
                 const float* __restrict__ W1, const float* __restrict__ b1,
                 const float* __restrict__ W2, const float* __restrict__ b2,
                 const float* __restrict__ W3, const float* __restrict__ b3,
                 float* __restrict__ out)
{
  extern __shared__ __align__(16) __half smh[];
  __half* Hh = smh + OFF_HH;
  __half* Xs = smh + OFF_XS;
  __half* Ws = smh + OFF_WS;

  const int tid  = threadIdx.x;
  const int lane = tid & 31;
  const int wid  = tid >> 5;
  const int wm   = wid >> 2;   // 0..1 (64-row blocks)
  const int wn   = wid & 3;    // 0..3 (col blocks)
  const int s0    = blockIdx.x * SAMP;
  const int nsamp = min(SAMP, TOTAL_B - s0);
  const int row0  = s0 * LEADS;

  float acc[4][8][4];

  auto zero_acc = [&]() {
    #pragma unroll
    for (int mi = 0; mi < 4; mi++)
      #pragma unroll
      for (int nj = 0; nj < 8; nj++)
        #pragma unroll
        for (int q = 0; q < 4; q++) acc[mi][nj][q] = 0.f;
  };

  // Epilogue: fp32 accumulators -> fp16 into Hh
  auto store_acc = [&](int wcols, int ntiles) {
    const int g = lane >> 2, t2 = (lane & 3) * 2;
    #pragma unroll
    for (int mi = 0; mi < 4; mi++)
      #pragma unroll
      for (int nj = 0; nj < 8; nj++) {
        if (nj >= ntiles) break;
        int row = wm * 64 + mi * 16 + g;
        int col = wn * wcols + nj * 8 + t2;
        *reinterpret_cast<__half2*>(Hh + row * SHH + col) =
            __floats2half2_rn(acc[mi][nj][0], acc[mi][nj][1]);
        *reinterpret_cast<__half2*>(Hh + (row + 8) * SHH + col) =
            __floats2half2_rn(acc[mi][nj][2], acc[mi][nj][3]);
      }
  };

  // Lead-mix + bias + relu, fp16 in place in Hh (processes column pairs)
  auto mixH = [&](const float* bias) {
    const int ntask = nsamp * (HID / 2);
    for (int tk = tid; tk < ntask; tk += NT) {
      int s = tk >> 7, cp = tk & 127;
      __half* base = Hh + (s * LEADS) * SHH + cp * 2;
      float2 v[12];
      #pragma unroll
      for (int l = 0; l < 12; l++)
        v[l] = __half22float2(*reinterpret_cast<__half2*>(base + l * SHH));
      float bx = bias[cp * 2], by = bias[cp * 2 + 1];
      #pragma unroll
      for (int n = 0; n < 12; n++) {
        float hx = bx, hy = by;
        #pragma unroll
        for (int m = 0; m < 12; m++) {
          if (AMC.a[n][m] != 0.f) {
            hx = fmaf(AMC.a[n][m], v[m].x, hx);
            hy = fmaf(AMC.a[n][m], v[m].y, hy);
          }
        }
        *reinterpret_cast<__half2*>(base + n * SHH) =
            __floats2half2_rn(fmaxf(hx, 0.f), fmaxf(hy, 0.f));
      }
    }
  };

  // ======================= Layer 1: X(128x512) @ W1(512x256) =======================
  {
    zero_acc();
    float4 px[4];
    float2 wv[16];

    // X stage: 128 rows x 32 halves -> 1024 float4 source reads, 4/thread
    auto ldx = [&](int kb) {
      #pragma unroll
      for (int i = 0; i < 4; i++) {
        int idx = tid + i * NT;
        int xr = idx >> 3, gq = idx & 7;
        int gr = row0 + xr;
        px[i] = (gr < TOTAL_ROWS)
                    ? *reinterpret_cast<const float4*>(x + (size_t)gr * FIN + kb + gq * 4)
                    : make_float4(0.f, 0.f, 0.f, 0.f);
      }
    };
    auto stx = [&](int buf) {
      #pragma unroll
      for (int i = 0; i < 4; i++) {
        int idx = tid + i * NT;
        int xr = idx >> 3, gq = idx & 7;
        uint2 u;
        u.x = h2u(__floats2half2_rn(px[i].x, px[i].y));
        u.y = h2u(__floats2half2_rn(px[i].z, px[i].w));
        *reinterpret_cast<uint2*>(Xs + buf * XBUF + xr * SA + gq * 4) = u;
      }
    };
    // W stage (transpose to [n][k]): thread owns n = tid, 16 k-pairs
    auto ldw = [&](int kb) {
      #pragma unroll
      for (int j = 0; j < 16; j++) {
        wv[j].x = W1[(size_t)(kb + 2 * j) * HID + tid];
        wv[j].y = W1[(size_t)(kb + 2 * j + 1) * HID + tid];
      }
    };
    auto stw = [&](int buf) {
      #pragma unroll
      for (int j = 0; j < 16; j++)
        *reinterpret_cast<__half2*>(Ws + buf * WBUF + tid * SB + 2 * j) =
            __floats2half2_rn(wv[j].x, wv[j].y);
    };

    ldx(0); ldw(0);
    stx(0); stw(0);
    __syncthreads();
    constexpr int NC = FIN / KC;   // 16 chunks
    for (int ck = 0; ck < NC; ck++) {
      if (ck + 1 < NC) { ldx((ck + 1) * KC); ldw((ck + 1) * KC); }
      gemm_chunk<8>(Xs + (ck & 1) * XBUF + (wm * 64) * SA, SA,
                    Ws + (ck & 1) * WBUF + (wn * 64) * SB, SB, lane, acc);
      if (ck + 1 < NC) { stx((ck + 1) & 1); stw((ck + 1) & 1); }
      __syncthreads();
    }
    store_acc(64, 8);
    __syncthreads();
    mixH(b1);
    __syncthreads();
  }

  // ======================= Layer 2: H(128x256) @ W2(256x256) =======================
  {
    zero_acc();
    float2 wv[16];
    auto ldw2 = [&](int kb) {
      #pragma unroll
      for (int j = 0; j < 16; j++) {
        wv[j].x = W2[(size_t)(kb + 2 * j) * HID + tid];
        wv[j].y = W2[(size_t)(kb + 2 * j + 1) * HID + tid];
      }
    };
    auto stw2 = [&](int buf) {
      #pragma unroll
      for (int j = 0; j < 16; j++)
        *reinterpret_cast<__half2*>(Ws + buf * WBUF + tid * SB + 2 * j) =
            __floats2half2_rn(wv[j].x, wv[j].y);
    };

    ldw2(0); stw2(0);
    __syncthreads();
    constexpr int NC2 = HID / KC;   // 8 chunks
    for (int ck = 0; ck < NC2; ck++) {
      if (ck + 1 < NC2) ldw2((ck + 1) * KC);
      gemm_chunk<8>(Hh + (wm * 64) * SHH + ck * KC, SHH,
                    Ws + (ck & 1) * WBUF + (wn * 64) * SB, SB, lane, acc);
      if (ck + 1 < NC2) stw2((ck + 1) & 1);
      __syncthreads();
    }
    store_acc(64, 8);
    __syncthreads();
    mixH(b2);
    __syncthreads();
  }

  // ======================= Layer 3: H(128x256) @ W3(256x128) + pool =======================
  {
    zero_acc();
    float2 wv3[8];
    const int n3 = tid & 127, kph = tid >> 7;
    auto ldw3 = [&](int kb) {
      #pragma unroll
      for (int j = 0; j < 8; j++) {
        int kp = kph + 2 * j;
        wv3[j].x = W3[(size_t)(kb + 2 * kp) * OUTF + n3];
        wv3[j].y = W3[(size_t)(kb + 2 * kp + 1) * OUTF + n3];
      }
    };
    auto stw3 = [&](int buf) {
      #pragma unroll
      for (int j = 0; j < 8; j++) {
        int kp = kph + 2 * j;
        *reinterpret_cast<__half2*>(Ws + buf * WBUF + n3 * SB + 2 * kp) =
            __floats2half2_rn(wv3[j].x, wv3[j].y);
      }
    };

    ldw3(0); stw3(0);
    __syncthreads();
    constexpr int NC3 = HID / KC;   // 8 chunks
    for (int ck = 0; ck < NC3; ck++) {
      if (ck + 1 < NC3) ldw3((ck + 1) * KC);
      gemm_chunk<4>(Hh + (wm * 64) * SHH + ck * KC, SHH,
                    Ws + (ck & 1) * WBUF + (wn * 32) * SB, SB, lane, acc);
      if (ck + 1 < NC3) stw3((ck + 1) & 1);
      __syncthreads();
    }
    store_acc(32, 4);
    __syncthreads();

    // Final: lead-mix + b3, mean/max pool over leads, write (B, 2*OUTF)
    const int ntask = nsamp * (OUTF / 2);
    for (int tk = tid; tk < ntask; tk += NT) {
      int s = tk >> 6, cp = tk & 63;
      const __half* base = Hh + (s * LEADS) * SHH + cp * 2;
      float2 v[12];
      #pragma unroll
      for (int l = 0; l < 12; l++)
        v[l] = __half22float2(*reinterpret_cast<const __half2*>(base + l * SHH));
      float bx = b3[cp * 2], by = b3[cp * 2 + 1];
      float meanx = 0.f, meany = 0.f;
      float mxx = __int_as_float(0xff800000), mxy = mxx;
      #pragma unroll
      for (int n = 0; n < 12; n++) {
        float hx = bx, hy = by;
        #pragma unroll
        for (int m = 0; m < 12; m++) {
          if (AMC.a[n][m] != 0.f) {
            hx = fmaf(AMC.a[n][m], v[m].x, hx);
            hy = fmaf(AMC.a[n][m], v[m].y, hy);
          }
        }
        meanx += hx; meany += hy;
        mxx = fmaxf(mxx, hx); mxy = fmaxf(mxy, hy);
      }
      size_t ob = (size_t)(s0 + s) * (2 * OUTF);
      *reinterpret_cast<float2*>(out + ob + cp * 2) =
          make_float2(meanx * (1.f / 12.f), meany * (1.f / 12.f));
      *reinterpret_cast<float2*>(out + ob + OUTF + cp * 2) = make_float2(mxx, mxy);
    }
  }
}

} // anonymous namespace

extern "C" void kernel_launch(void* const* d_in, const int* in_sizes, int n_in,
                              void* d_out, int out_size) {
  const float* x  = (const float*)d_in[0];
  const float* W1 = (const float*)d_in[1];
  const float* b1 = (const float*)d_in[2];
  const float* W2 = (const float*)d_in[3];
  const float* b2 = (const float*)d_in[4];
  const float* W3 = (const float*)d_in[5];
  const float* b3 = (const float*)d_in[6];
  float* out = (float*)d_out;

  cudaFuncSetAttribute(ecg_fused_kernel,
                       cudaFuncAttributeMaxDynamicSharedMemorySize, SMEM_BYTES);

  const int grid = (TOTAL_B + SAMP - 1) / SAMP;   // 1639
  ecg_fused_kernel<<<grid, NT, SMEM_BYTES>>>(x, W1, b1, W2, b2, W3, b3, out);
}

// round 12
// speedup vs baseline: 2.2904x; 1.0652x over previous
#include <cuda_runtime.h>
#include <cuda_fp16.h>
#include <cstdint>

#define DEV __device__ __forceinline__

namespace {

constexpr int LEADS = 12;
constexpr int FIN   = 512;
constexpr int HID   = 256;
constexpr int OUTF  = 128;
constexpr int TOTAL_B = 16384;
constexpr int TOTAL_ROWS = TOTAL_B * LEADS;   // 196608

constexpr int SAMP = 10;       // samples per CTA -> 120 rows, pad to 128
constexpr int NT   = 256;      // 8 warps, 64x64 warp tiles
constexpr int KC   = 32;       // K halves per streamed chunk (2 x k16 mma steps)

// strides in halves. Conflict-free for ldmatrix: 8 consecutive rows' 16B
// segments must cover disjoint bank quads -> (stride_words % 32) pattern
// {20r} or {4r} mod 32 disjoint. SA/SB=40 (20 words), SHH=264 (132 words). OK.
constexpr int SA  = 40;        // staged A (X) row stride
constexpr int SB  = 40;        // staged B (W^T) row stride
constexpr int SHH = 264;       // H buffer row stride

constexpr int XBUF = 128 * SA;     // 5120 halves per buffer
constexpr int WBUF = 256 * SB;     // 10240 halves per buffer (20480 B)

// SMEM layout (halves)
constexpr int OFF_HH = 0;                       // 128 x 264 = 33792
constexpr int OFF_XS = 128 * SHH;               // 2 x XBUF
constexpr int OFF_WS = OFF_XS + 2 * XBUF;       // 2 x WBUF
constexpr int SMEM_HALVES = OFF_WS + 2 * WBUF;  // 64512
constexpr int SMEM_BYTES  = SMEM_HALVES * 2;    // 129024 B

// Weight scratch: pre-transposed fp16 panels in EXACT SMEM layout (incl. SB pad)
constexpr int WCH  = 256 * SB;   // 10240 halves per chunk (W1/W2)
constexpr int WCH3 = 128 * SB;   // 5120 halves per chunk (W3)
__device__ __half g_w1t[(FIN / KC) * WCH];   // 16 chunks
__device__ __half g_w2t[(HID / KC) * WCH];   // 8 chunks
__device__ __half g_w3t[(HID / KC) * WCH3];  // 8 chunks

// ---- compile-time normalized adjacency (matches reference _norm_adj) ----
constexpr double csqrt(double x) {
  double g = x > 1.0 ? x : 1.0;
  for (int i = 0; i < 64; i++) g = 0.5 * (g + x / g);
  return g;
}
struct AMt { float a[12][12]; };
constexpr AMt make_am() {
  AMt m{};
  const int ci[15] = {0,0,1,0,1,2,0,1,1,2,6,7,8,9,10};
  const int cj[15] = {1,2,2,3,3,3,4,4,5,5,7,8,9,10,11};
  double ae[12][12] = {};
  for (int p = 0; p < 15; p++) { ae[ci[p]][cj[p]] = 1.0; ae[cj[p]][ci[p]] = 1.0; }
  for (int i = 0; i < 12; i++) ae[i][i] = 2.0;
  double deg[12] = {};
  for (int i = 0; i < 12; i++)
    for (int j = 0; j < 12; j++) deg[i] += ae[i][j];
  for (int i = 0; i < 12; i++)
    for (int j = 0; j < 12; j++)
      m.a[i][j] = (float)(ae[i][j] / (csqrt(deg[i]) * csqrt(deg[j])));
  return m;
}
__device__ constexpr AMt AMC = make_am();

DEV uint32_t h2u(__half2 h) { return *reinterpret_cast<uint32_t*>(&h); }

DEV void mma16(float d[4], const uint32_t a[4], uint32_t b0, uint32_t b1) {
  asm volatile(
    "mma.sync.aligned.m16n8k16.row.col.f32.f16.f16.f32 "
    "{%0,%1,%2,%3},{%4,%5,%6,%7},{%8,%9},{%0,%1,%2,%3};"
    : "+f"(d[0]), "+f"(d[1]), "+f"(d[2]), "+f"(d[3])
    : "r"(a[0]), "r"(a[1]), "r"(a[2]), "r"(a[3]), "r"(b0), "r"(b1));
}

DEV void ldm_x4(uint32_t r[4], uint32_t saddr) {
  asm volatile("ldmatrix.sync.aligned.m8n8.x4.shared.b16 {%0,%1,%2,%3}, [%4];"
               : "=r"(r[0]), "=r"(r[1]), "=r"(r[2]), "=r"(r[3]) : "r"(saddr));
}

DEV void cpa16(uint32_t dst, const void* src) {
  asm volatile("cp.async.ca.shared.global [%0], [%1], 16;"
               :: "r"(dst), "l"(src) : "memory");
}
#define CPA_COMMIT() asm volatile("cp.async.commit_group;" ::: "memory")
#define CPA_WAIT0()  asm volatile("cp.async.wait_group 0;" ::: "memory")

// Warp-level 64 x (NTILES*8) GEMM over one KC=32 chunk (two k16 steps).
// As: warp's 64-row block base, [row][k] halves stride sa.
// Bs: warp's n-block base, [n][k] halves stride sb. ldmatrix fragment loads.
template<int NTILES>
DEV void gemm_chunk(const __half* __restrict__ As, int sa,
                    const __half* __restrict__ Bs, int sb,
                    int lane, float acc[4][8][4]) {
  const int l7 = lane & 7, lb8 = (lane >> 3) & 1, lb16 = lane >> 4;
  #pragma unroll
  for (int k0 = 0; k0 < KC; k0 += 16) {
    uint32_t a[4][4];
    #pragma unroll
    for (int mi = 0; mi < 4; mi++) {
      // matrices: {rows 0-7,k0-7},{rows 8-15,k0-7},{rows 0-7,k8-15},{rows 8-15,k8-15}
      const __half* ap = As + (mi * 16 + lb8 * 8 + l7) * sa + k0 + lb16 * 8;
      ldm_x4(a[mi], (uint32_t)__cvta_generic_to_shared(ap));
    }
    uint32_t b[NTILES][2];
    #pragma unroll
    for (int np = 0; np < NTILES / 2; np++) {
      // matrices: {njA,k0-7},{njA,k8-15},{njB,k0-7},{njB,k8-15}
      const __half* bp = Bs + ((2 * np + lb16) * 8 + l7) * sb + k0 + lb8 * 8;
      uint32_t t[4];
      ldm_x4(t, (uint32_t)__cvta_generic_to_shared(bp));
      b[2 * np][0] = t[0]; b[2 * np][1] = t[1];
      b[2 * np + 1][0] = t[2]; b[2 * np + 1][1] = t[3];
    }
    #pragma unroll
    for (int nj = 0; nj < NTILES; nj++)
      #pragma unroll
      for (int mi = 0; mi < 4; mi++)
        mma16(acc[mi][nj], a[mi], b[nj][0], b[nj][1]);
  }
}

// ---- one-shot: transpose + fp16-convert weights into panel-layout scratch ----
__global__ void conv_w_kernel(const float* __restrict__ W1,
                              const float* __restrict__ W2,
                              const float* __restrict__ W3) {
  int id = blockIdx.x * blockDim.x + threadIdx.x;   // 0 .. 131071
  if (id < FIN * HID) {            // W1: [512][256]
    int k = id >> 8, n = id & 255;
    g_w1t[(k >> 5) * WCH + n * SB + (k & 31)] = __float2half(W1[id]);
  }
  if (id < HID * HID) {            // W2: [256][256]
    int k = id >> 8, n = id & 255;
    g_w2t[(k >> 5) * WCH + n * SB + (k & 31)] = __float2half(W2[id]);
  }
  if (id < HID * OUTF) {           // W3: [256][128]
    int k = id >> 7, n = id & 127;
    g_w3t[(k >> 5) * WCH3 + n * SB + (k & 31)] = __float2half(W3[id]);
  }
}

__global__ void __launch_bounds__(NT, 1)
ecg_fused_kernel(const float* __restrict__ x,
                 const float* __restrict__ b1,
                 const float* __restrict__ b2,
                 const float* __restrict__ b3,
                 float* __restrict__ out)
{
  extern __shared__ __align__(16) __half smh[];
  __half* Hh = smh + OFF_HH;
  __half* Xs = smh + OFF_XS;
  __half* Ws = smh + OFF_WS;

  const int tid  = threadIdx.x;
  const int lane = tid & 31;
  const int wid  = tid >> 5;
  const int wm   = wid >> 2;   // 0..1 (64-row blocks)
  const int wn   = wid & 3;    // 0..3 (col blocks)
  const int s0    = blockIdx.x * SAMP;
  const int nsamp = min(SAMP, TOTAL_B - s0);
  const int row0  = s0 * LEADS;

  const uint32_t ws_addr = (uint32_t)__cvta_generic_to_shared(Ws);

  float acc[4][8][4];

  auto zero_acc = [&]() {
    #pragma unroll
    for (int mi = 0; mi < 4; mi++)
      #pragma unroll
      for (int nj = 0; nj < 8; nj++)
        #pragma unroll
        for (int q = 0; q < 4; q++) acc[mi][nj][q] = 0.f;
  };

  // Async copy one pre-laid-out W chunk into Ws buffer `buf`. n16 = 16B units.
  auto issue_w = [&](const __half* gsrc, int buf, int n16) {
    uint32_t base = ws_addr + (uint32_t)buf * (WBUF * 2);
    const char* src = reinterpret_cast<const char*>(gsrc);
    for (int i = tid; i < n16; i += NT)
      cpa16(base + i * 16, src + i * 16);
    CPA_COMMIT();
  };

  // Epilogue: fp32 accumulators -> fp16 into Hh
  auto store_acc = [&](int wcols, int ntiles) {
    const int g = lane >> 2, t2 = (lane & 3) * 2;
    #pragma unroll
    for (int mi = 0; mi < 4; mi++)
      #pragma unroll
      for (int nj = 0; nj < 8; nj++) {
        if (nj >= ntiles) break;
        int row = wm * 64 + mi * 16 + g;
        int col = wn * wcols + nj * 8 + t2;
        *reinterpret_cast<__half2*>(Hh + row * SHH + col) =
            __floats2half2_rn(acc[mi][nj][0], acc[mi][nj][1]);
        *reinterpret_cast<__half2*>(Hh + (row + 8) * SHH + col) =
            __floats2half2_rn(acc[mi][nj][2], acc[mi][nj][3]);
      }
  };

  // Lead-mix + bias + relu, fp16 in place in Hh (column pairs)
  auto mixH = [&](const float* bias) {
    const int ntask = nsamp * (HID / 2);
    for (int tk = tid; tk < ntask; tk += NT) {
      int s = tk >> 7, cp = tk & 127;
      __half* base = Hh + (s * LEADS) * SHH + cp * 2;
      float2 v[12];
      #pragma unroll
      for (int l = 0; l < 12; l++)
        v[l] = __half22float2(*reinterpret_cast<__half2*>(base + l * SHH));
      float bx = bias[cp * 2], by = bias[cp * 2 + 1];
      #pragma unroll
      for (int n = 0; n < 12; n++) {
        float hx = bx, hy = by;
        #pragma unroll
        for (int m = 0; m < 12; m++) {
          if (AMC.a[n][m] != 0.f) {
            hx = fmaf(AMC.a[n][m], v[m].x, hx);
            hy = fmaf(AMC.a[n][m], v[m].y, hy);
          }
        }
        *reinterpret_cast<__half2*>(base + n * SHH) =
            __floats2half2_rn(fmaxf(hx, 0.f), fmaxf(hy, 0.f));
      }
    }
  };

  // ======================= Layer 1: X(128x512) @ W1(512x256) =======================
  {
    zero_acc();
    float4 px[4];

    auto ldx = [&](int kb) {
      #pragma unroll
      for (int i = 0; i < 4; i++) {
        int idx = tid + i * NT;
        int xr = idx >> 3, gq = idx & 7;
        int gr = row0 + xr;
        px[i] = (gr < TOTAL_ROWS)
                    ? *reinterpret_cast<const float4*>(x + (size_t)gr * FIN + kb + gq * 4)
                    : make_float4(0.f, 0.f, 0.f, 0.f);
      }
    };
    auto stx = [&](int buf) {
      #pragma unroll
      for (int i = 0; i < 4; i++) {
        int idx = tid + i * NT;
        int xr = idx >> 3, gq = idx & 7;
        uint2 u;
        u.x = h2u(__floats2half2_rn(px[i].x, px[i].y));
        u.y = h2u(__floats2half2_rn(px[i].z, px[i].w));
        *reinterpret_cast<uint2*>(Xs + buf * XBUF + xr * SA + gq * 4) = u;
      }
    };

    ldx(0);
    issue_w(g_w1t, 0, 1280);
    stx(0);
    CPA_WAIT0();
    __syncthreads();
    constexpr int NC = FIN / KC;   // 16 chunks
    for (int ck = 0; ck < NC; ck++) {
      if (ck + 1 < NC) { ldx((ck + 1) * KC); issue_w(g_w1t + (ck + 1) * WCH, (ck + 1) & 1, 1280); }
      gemm_chunk<8>(Xs + (ck & 1) * XBUF + (wm * 64) * SA, SA,
                    Ws + (ck & 1) * WBUF + (wn * 64) * SB, SB, lane, acc);
      if (ck + 1 < NC) stx((ck + 1) & 1);
      CPA_WAIT0();
      __syncthreads();
    }
    store_acc(64, 8);
    __syncthreads();
    mixH(b1);
    __syncthreads();
  }

  // ======================= Layer 2: H(128x256) @ W2(256x256) =======================
  {
    zero_acc();
    issue_w(g_w2t, 0, 1280);
    CPA_WAIT0();
    __syncthreads();
    constexpr int NC2 = HID / KC;   // 8 chunks
    for (int ck = 0; ck < NC2; ck++) {
      if (ck + 1 < NC2) issue_w(g_w2t + (ck + 1) * WCH, (ck + 1) & 1, 1280);
      gemm_chunk<8>(Hh + (wm * 64) * SHH + ck * KC, SHH,
                    Ws + (ck & 1) * WBUF + (wn * 64) * SB, SB, lane, acc);
      CPA_WAIT0();
      __syncthreads();
    }
    store_acc(64, 8);
    __syncthreads();
    mixH(b2);
    __syncthreads();
  }

  // ======================= Layer 3: H(128x256) @ W3(256x128) + pool =======================
  {
    zero_acc();
    issue_w(g_w3t, 0, 640);
    CPA_WAIT0();
    __syncthreads();
    constexpr int NC3 = HID / KC;   // 8 chunks
    for (int ck = 0; ck < NC3; ck++) {
      if (ck + 1 < NC3) issue_w(g_w3t + (ck + 1) * WCH3, (ck + 1) & 1, 640);
      gemm_chunk<4>(Hh + (wm * 64) * SHH + ck * KC, SHH,
                    Ws + (ck & 1) * WBUF + (wn * 32) * SB, SB, lane, acc);
      CPA_WAIT0();
      __syncthreads();
    }
    store_acc(32, 4);
    __syncthreads();

    // Final: lead-mix + b3, mean/max pool over leads, write (B, 2*OUTF)
    const int ntask = nsamp * (OUTF / 2);
    for (int tk = tid; tk < ntask; tk += NT) {
      int s = tk >> 6, cp = tk & 63;
      const __half* base = Hh + (s * LEADS) * SHH + cp * 2;
      float2 v[12];
      #pragma unroll
      for (int l = 0; l < 12; l++)
        v[l] = __half22float2(*reinterpret_cast<const __half2*>(base + l * SHH));
      float bx = b3[cp * 2], by = b3[cp * 2 + 1];
      float meanx = 0.f, meany = 0.f;
      float mxx = __int_as_float(0xff800000), mxy = mxx;
      #pragma unroll
      for (int n = 0; n < 12; n++) {
        float hx = bx, hy = by;
        #pragma unroll
        for (int m = 0; m < 12; m++) {
          if (AMC.a[n][m] != 0.f) {
            hx = fmaf(AMC.a[n][m], v[m].x, hx);
            hy = fmaf(AMC.a[n][m], v[m].y, hy);
          }
        }
        meanx += hx; meany += hy;
        mxx = fmaxf(mxx, hx); mxy = fmaxf(mxy, hy);
      }
      size_t ob = (size_t)(s0 + s) * (2 * OUTF);
      *reinterpret_cast<float2*>(out + ob + cp * 2) =
          make_float2(meanx * (1.f / 12.f), meany * (1.f / 12.f));
      *reinterpret_cast<float2*>(out + ob + OUTF + cp * 2) = make_float2(mxx, mxy);
    }
  }
}

} // anonymous namespace

extern "C" void kernel_launch(void* const* d_in, const int* in_sizes, int n_in,
                              void* d_out, int out_size) {
  const float* x  = (const float*)d_in[0];
  const float* W1 = (const float*)d_in[1];
  const float* b1 = (const float*)d_in[2];
  const float* W2 = (const float*)d_in[3];
  const float* b2 = (const float*)d_in[4];
  const float* W3 = (const float*)d_in[5];
  const float* b3 = (const float*)d_in[6];
  float* out = (float*)d_out;

  // one-shot weight transpose+convert into panel-layout scratch
  conv_w_kernel<<<(FIN * HID + 255) / 256, 256>>>(W1, W2, W3);

  cudaFuncSetAttribute(ecg_fused_kernel,
                       cudaFuncAttributeMaxDynamicSharedMemorySize, SMEM_BYTES);

  const int grid = (TOTAL_B + SAMP - 1) / SAMP;   // 1639
  ecg_fused_kernel<<<grid, NT, SMEM_BYTES>>>(x, b1, b2, b3, out);
}

// round 13
// speedup vs baseline: 2.3564x; 1.0288x over previous
#include <cuda_runtime.h>
#include <cuda_fp16.h>
#include <cstdint>

#define DEV __device__ __forceinline__

namespace {

constexpr int LEADS = 12;
constexpr int FIN   = 512;
constexpr int HID   = 256;
constexpr int OUTF  = 128;
constexpr int TOTAL_B = 16384;
constexpr int TOTAL_ROWS = TOTAL_B * LEADS;   // 196608

constexpr int SAMP = 10;       // samples per CTA -> 120 rows, pad to 128
constexpr int NT   = 512;      // 16 warps, 64x32 warp tiles (2m x 8n)
constexpr int KC   = 32;       // K halves per streamed chunk (2 x k16 mma steps)

// strides in halves (ldmatrix conflict-free: see R12 analysis)
constexpr int SA  = 40;        // staged A (X) row stride
constexpr int SB  = 40;        // staged B (W^T) row stride
constexpr int SHH = 264;       // H buffer row stride

constexpr int XBUF = 128 * SA;     // 5120 halves per buffer
constexpr int WBUF = 256 * SB;     // 10240 halves per buffer (20480 B)

// SMEM layout (halves)
constexpr int OFF_HH = 0;                       // 128 x 264 = 33792
constexpr int OFF_XS = 128 * SHH;               // 2 x XBUF
constexpr int OFF_WS = OFF_XS + 2 * XBUF;       // 2 x WBUF
constexpr int SMEM_HALVES = OFF_WS + 2 * WBUF;  // 64512
constexpr int SMEM_BYTES  = SMEM_HALVES * 2;    // 129024 B

// Weight scratch: pre-transposed fp16 panels in EXACT SMEM layout (incl. SB pad)
constexpr int WCH  = 256 * SB;   // 10240 halves per chunk (W1/W2)
constexpr int WCH3 = 128 * SB;   // 5120 halves per chunk (W3)
__device__ __half g_w1t[(FIN / KC) * WCH];   // 16 chunks
__device__ __half g_w2t[(HID / KC) * WCH];   // 8 chunks
__device__ __half g_w3t[(HID / KC) * WCH3];  // 8 chunks

// ---- compile-time normalized adjacency (matches reference _norm_adj) ----
constexpr double csqrt(double x) {
  double g = x > 1.0 ? x : 1.0;
  for (int i = 0; i < 64; i++) g = 0.5 * (g + x / g);
  return g;
}
struct AMt { float a[12][12]; };
constexpr AMt make_am() {
  AMt m{};
  const int ci[15] = {0,0,1,0,1,2,0,1,1,2,6,7,8,9,10};
  const int cj[15] = {1,2,2,3,3,3,4,4,5,5,7,8,9,10,11};
  double ae[12][12] = {};
  for (int p = 0; p < 15; p++) { ae[ci[p]][cj[p]] = 1.0; ae[cj[p]][ci[p]] = 1.0; }
  for (int i = 0; i < 12; i++) ae[i][i] = 2.0;
  double deg[12] = {};
  for (int i = 0; i < 12; i++)
    for (int j = 0; j < 12; j++) deg[i] += ae[i][j];
  for (int i = 0; i < 12; i++)
    for (int j = 0; j < 12; j++)
      m.a[i][j] = (float)(ae[i][j] / (csqrt(deg[i]) * csqrt(deg[j])));
  return m;
}
__device__ constexpr AMt AMC = make_am();

DEV uint32_t h2u(__half2 h) { return *reinterpret_cast<uint32_t*>(&h); }

DEV void mma16(float d[4], const uint32_t a[4], uint32_t b0, uint32_t b1) {
  asm volatile(
    "mma.sync.aligned.m16n8k16.row.col.f32.f16.f16.f32 "
    "{%0,%1,%2,%3},{%4,%5,%6,%7},{%8,%9},{%0,%1,%2,%3};"
    : "+f"(d[0]), "+f"(d[1]), "+f"(d[2]), "+f"(d[3])
    : "r"(a[0]), "r"(a[1]), "r"(a[2]), "r"(a[3]), "r"(b0), "r"(b1));
}

DEV void ldm_x4(uint32_t r[4], uint32_t saddr) {
  asm volatile("ldmatrix.sync.aligned.m8n8.x4.shared.b16 {%0,%1,%2,%3}, [%4];"
               : "=r"(r[0]), "=r"(r[1]), "=r"(r[2]), "=r"(r[3]) : "r"(saddr));
}

DEV void cpa16(uint32_t dst, const void* src) {
  asm volatile("cp.async.ca.shared.global [%0], [%1], 16;"
               :: "r"(dst), "l"(src) : "memory");
}
#define CPA_COMMIT() asm volatile("cp.async.commit_group;" ::: "memory")
#define CPA_WAIT0()  asm volatile("cp.async.wait_group 0;" ::: "memory")

// Warp-level 64 x (NTILES*8) GEMM over one KC=32 chunk (two k16 steps).
template<int NTILES>
DEV void gemm_chunk(const __half* __restrict__ As, int sa,
                    const __half* __restrict__ Bs, int sb,
                    int lane, float acc[4][4][4]) {
  const int l7 = lane & 7, lb8 = (lane >> 3) & 1, lb16 = lane >> 4;
  #pragma unroll
  for (int k0 = 0; k0 < KC; k0 += 16) {
    uint32_t a[4][4];
    #pragma unroll
    for (int mi = 0; mi < 4; mi++) {
      const __half* ap = As + (mi * 16 + lb8 * 8 + l7) * sa + k0 + lb16 * 8;
      ldm_x4(a[mi], (uint32_t)__cvta_generic_to_shared(ap));
    }
    uint32_t b[NTILES][2];
    #pragma unroll
    for (int np = 0; np < NTILES / 2; np++) {
      const __half* bp = Bs + ((2 * np + lb16) * 8 + l7) * sb + k0 + lb8 * 8;
      uint32_t t[4];
      ldm_x4(t, (uint32_t)__cvta_generic_to_shared(bp));
      b[2 * np][0] = t[0]; b[2 * np][1] = t[1];
      b[2 * np + 1][0] = t[2]; b[2 * np + 1][1] = t[3];
    }
    #pragma unroll
    for (int nj = 0; nj < NTILES; nj++)
      #pragma unroll
      for (int mi = 0; mi < 4; mi++)
        mma16(acc[mi][nj], a[mi], b[nj][0], b[nj][1]);
  }
}

// ---- one-shot: transpose + fp16-convert weights into panel-layout scratch ----
__global__ void conv_w_kernel(const float* __restrict__ W1,
                              const float* __restrict__ W2,
                              const float* __restrict__ W3) {
  int id = blockIdx.x * blockDim.x + threadIdx.x;   // 0 .. 131071
  if (id < FIN * HID) {            // W1: [512][256]
    int k = id >> 8, n = id & 255;
    g_w1t[(k >> 5) * WCH + n * SB + (k & 31)] = __float2half(W1[id]);
  }
  if (id < HID * HID) {            // W2: [256][256]
    int k = id >> 8, n = id & 255;
    g_w2t[(k >> 5) * WCH + n * SB + (k & 31)] = __float2half(W2[id]);
  }
  if (id < HID * OUTF) {           // W3: [256][128]
    int k = id >> 7, n = id & 127;
    g_w3t[(k >> 5) * WCH3 + n * SB + (k & 31)] = __float2half(W3[id]);
  }
}

__global__ void __launch_bounds__(NT, 1)
ecg_fused_kernel(const float* __restrict__ x,
                 const float* __restrict__ b1,
                 const float* __restrict__ b2,
                 const float* __restrict__ b3,
                 float* __restrict__ out)
{
  extern __shared__ __align__(16) __half smh[];
  __half* Hh = smh + OFF_HH;
  __half* Xs = smh + OFF_XS;
  __half* Ws = smh + OFF_WS;

  const int tid  = threadIdx.x;
  const int lane = tid & 31;
  const int wid  = tid >> 5;
  const int wm   = wid >> 3;   // 0..1 (64-row blocks)
  const int wn   = wid & 7;    // 0..7 (col blocks)
  const int s0    = blockIdx.x * SAMP;
  const int nsamp = min(SAMP, TOTAL_B - s0);
  const int row0  = s0 * LEADS;

  const uint32_t ws_addr = (uint32_t)__cvta_generic_to_shared(Ws);

  float acc[4][4][4];

  auto zero_acc = [&]() {
    #pragma unroll
    for (int mi = 0; mi < 4; mi++)
      #pragma unroll
      for (int nj = 0; nj < 4; nj++)
        #pragma unroll
        for (int q = 0; q < 4; q++) acc[mi][nj][q] = 0.f;
  };

  // Async copy one pre-laid-out W chunk into Ws buffer `buf`. n16 = 16B units.
  auto issue_w = [&](const __half* gsrc, int buf, int n16) {
    uint32_t base = ws_addr + (uint32_t)buf * (WBUF * 2);
    const char* src = reinterpret_cast<const char*>(gsrc);
    for (int i = tid; i < n16; i += NT)
      cpa16(base + i * 16, src + i * 16);
    CPA_COMMIT();
  };

  // Epilogue: fp32 accumulators -> fp16 into Hh
  auto store_acc = [&](int wcols, int ntiles) {
    const int g = lane >> 2, t2 = (lane & 3) * 2;
    #pragma unroll
    for (int mi = 0; mi < 4; mi++)
      #pragma unroll
      for (int nj = 0; nj < 4; nj++) {
        if (nj >= ntiles) break;
        int row = wm * 64 + mi * 16 + g;
        int col = wn * wcols + nj * 8 + t2;
        *reinterpret_cast<__half2*>(Hh + row * SHH + col) =
            __floats2half2_rn(acc[mi][nj][0], acc[mi][nj][1]);
        *reinterpret_cast<__half2*>(Hh + (row + 8) * SHH + col) =
            __floats2half2_rn(acc[mi][nj][2], acc[mi][nj][3]);
      }
  };

  // Lead-mix + bias + relu, fp16 in place in Hh (column pairs)
  auto mixH = [&](const float* bias) {
    const int ntask = nsamp * (HID / 2);
    for (int tk = tid; tk < ntask; tk += NT) {
      int s = tk >> 7, cp = tk & 127;
      __half* base = Hh + (s * LEADS) * SHH + cp * 2;
      float2 v[12];
      #pragma unroll
      for (int l = 0; l < 12; l++)
        v[l] = __half22float2(*reinterpret_cast<__half2*>(base + l * SHH));
      float bx = bias[cp * 2], by = bias[cp * 2 + 1];
      #pragma unroll
      for (int n = 0; n < 12; n++) {
        float hx = bx, hy = by;
        #pragma unroll
        for (int m = 0; m < 12; m++) {
          if (AMC.a[n][m] != 0.f) {
            hx = fmaf(AMC.a[n][m], v[m].x, hx);
            hy = fmaf(AMC.a[n][m], v[m].y, hy);
          }
        }
        *reinterpret_cast<__half2*>(base + n * SHH) =
            __floats2half2_rn(fmaxf(hx, 0.f), fmaxf(hy, 0.f));
      }
    }
  };

  // ======================= Layer 1: X(128x512) @ W1(512x256) =======================
  {
    zero_acc();
    float4 px[2];

    auto ldx = [&](int kb) {
      #pragma unroll
      for (int i = 0; i < 2; i++) {
        int idx = tid + i * NT;
        int xr = idx >> 3, gq = idx & 7;
        int gr = row0 + xr;
        px[i] = (gr < TOTAL_ROWS)
                    ? *reinterpret_cast<const float4*>(x + (size_t)gr * FIN + kb + gq * 4)
                    : make_float4(0.f, 0.f, 0.f, 0.f);
      }
    };
    auto stx = [&](int buf) {
      #pragma unroll
      for (int i = 0; i < 2; i++) {
        int idx = tid + i * NT;
        int xr = idx >> 3, gq = idx & 7;
        uint2 u;
        u.x = h2u(__floats2half2_rn(px[i].x, px[i].y));
        u.y = h2u(__floats2half2_rn(px[i].z, px[i].w));
        *reinterpret_cast<uint2*>(Xs + buf * XBUF + xr * SA + gq * 4) = u;
      }
    };

    ldx(0);
    issue_w(g_w1t, 0, 1280);
    stx(0);
    CPA_WAIT0();
    __syncthreads();
    constexpr int NC = FIN / KC;   // 16 chunks
    for (int ck = 0; ck < NC; ck++) {
      if (ck + 1 < NC) { ldx((ck + 1) * KC); issue_w(g_w1t + (ck + 1) * WCH, (ck + 1) & 1, 1280); }
      gemm_chunk<4>(Xs + (ck & 1) * XBUF + (wm * 64) * SA, SA,
                    Ws + (ck & 1) * WBUF + (wn * 32) * SB, SB, lane, acc);
      if (ck + 1 < NC) stx((ck + 1) & 1);
      CPA_WAIT0();
      __syncthreads();
    }
    // prefetch L2's first W chunk; lands during store_acc + mixH
    issue_w(g_w2t, 0, 1280);
    store_acc(32, 4);
    __syncthreads();
    mixH(b1);
    CPA_WAIT0();
    __syncthreads();
  }

  // ======================= Layer 2: H(128x256) @ W2(256x256) =======================
  {
    zero_acc();
    constexpr int NC2 = HID / KC;   // 8 chunks
    for (int ck = 0; ck < NC2; ck++) {
      if (ck + 1 < NC2) issue_w(g_w2t + (ck + 1) * WCH, (ck + 1) & 1, 1280);
      gemm_chunk<4>(Hh + (wm * 64) * SHH + ck * KC, SHH,
                    Ws + (ck & 1) * WBUF + (wn * 32) * SB, SB, lane, acc);
      CPA_WAIT0();
      __syncthreads();
    }
    // prefetch L3's first W chunk
    issue_w(g_w3t, 0, 640);
    store_acc(32, 4);
    __syncthreads();
    mixH(b2);
    CPA_WAIT0();
    __syncthreads();
  }

  // ======================= Layer 3: H(128x256) @ W3(256x128) + pool =======================
  {
    zero_acc();
    constexpr int NC3 = HID / KC;   // 8 chunks
    for (int ck = 0; ck < NC3; ck++) {
      if (ck + 1 < NC3) issue_w(g_w3t + (ck + 1) * WCH3, (ck + 1) & 1, 640);
      gemm_chunk<2>(Hh + (wm * 64) * SHH + ck * KC, SHH,
                    Ws + (ck & 1) * WBUF + (wn * 16) * SB, SB, lane, acc);
      CPA_WAIT0();
      __syncthreads();
    }
    store_acc(16, 2);
    __syncthreads();

    // Final: lead-mix + b3, mean/max pool over leads, write (B, 2*OUTF)
    const int ntask = nsamp * (OUTF / 2);
    for (int tk = tid; tk < ntask; tk += NT) {
      int s = tk >> 6, cp = tk & 63;
      const __half* base = Hh + (s * LEADS) * SHH + cp * 2;
      float2 v[12];
      #pragma unroll
      for (int l = 0; l < 12; l++)
        v[l] = __half22float2(*reinterpret_cast<const __half2*>(base + l * SHH));
      float bx = b3[cp * 2], by = b3[cp * 2 + 1];
      float meanx = 0.f, meany = 0.f;
      float mxx = __int_as_float(0xff800000), mxy = mxx;
      #pragma unroll
      for (int n = 0; n < 12; n++) {
        float hx = bx, hy = by;
        #pragma unroll
        for (int m = 0; m < 12; m++) {
          if (AMC.a[n][m] != 0.f) {
            hx = fmaf(AMC.a[n][m], v[m].x, hx);
            hy = fmaf(AMC.a[n][m], v[m].y, hy);
          }
        }
        meanx += hx; meany += hy;
        mxx = fmaxf(mxx, hx); mxy = fmaxf(mxy, hy);
      }
      size_t ob = (size_t)(s0 + s) * (2 * OUTF);
      *reinterpret_cast<float2*>(out + ob + cp * 2) =
          make_float2(meanx * (1.f / 12.f), meany * (1.f / 12.f));
      *reinterpret_cast<float2*>(out + ob + OUTF + cp * 2) = make_float2(mxx, mxy);
    }
  }
}

} // anonymous namespace

extern "C" void kernel_launch(void* const* d_in, const int* in_sizes, int n_in,
                              void* d_out, int out_size) {
  const float* x  = (const float*)d_in[0];
  const float* W1 = (const float*)d_in[1];
  const float* b1 = (const float*)d_in[2];
  const float* W2 = (const float*)d_in[3];
  const float* b2 = (const float*)d_in[4];
  const float* W3 = (const float*)d_in[5];
  const float* b3 = (const float*)d_in[6];
  float* out = (float*)d_out;

  // one-shot weight transpose+convert into panel-layout scratch
  conv_w_kernel<<<(FIN * HID + 255) / 256, 256>>>(W1, W2, W3);

  cudaFuncSetAttribute(ecg_fused_kernel,
                       cudaFuncAttributeMaxDynamicSharedMemorySize, SMEM_BYTES);

  const int grid = (TOTAL_B + SAMP - 1) / SAMP;   // 1639
  ecg_fused_kernel<<<grid, NT, SMEM_BYTES>>>(x, b1, b2, b3, out);
}